// round 3
// baseline (speedup 1.0000x reference)
#include <cuda_runtime.h>

#define NPL   50000
#define L_TOT 6
#define KN    8
#define FEAT  32
#define H     128
#define MT    32      // nodes per block
#define NT    128     // threads = H (thread t owns feature f=t)
#define MP    (MT/2)  // 16 packed m-pairs per thread
#define SP    36      // shared row stride in floats (144B: 16B-aligned, bank-spread)

typedef unsigned long long ull;

__device__ __forceinline__ ull pack2(float x, float y) {
    ull r; asm("mov.b64 %0, {%1, %2};" : "=l"(r) : "f"(x), "f"(y)); return r;
}
__device__ __forceinline__ void fma2(ull& acc, ull a, ull b) {
    asm("fma.rn.f32x2 %0, %1, %2, %0;" : "+l"(acc) : "l"(a), "l"(b));
}
__device__ __forceinline__ float2 unpack2(ull v) {
    float2 f; asm("mov.b64 {%0, %1}, %2;" : "=f"(f.x), "=f"(f.y) : "l"(v)); return f;
}
__device__ __forceinline__ float htanh(float x) {
    float y; asm("tanh.approx.f32 %0, %1;" : "=f"(y) : "f"(x)); return y;
}

// acc[mp] += S[k][2mp..2mp+1] * W[k][f]  over k in [0,H)
// S transposed: S[k][m], row stride SP floats. Packed pair = two nodes, one weight.
__device__ __forceinline__ void accum_t(const float* __restrict__ S,
                                        const float* __restrict__ W,
                                        int f, ull acc[MP])
{
#pragma unroll 2
    for (int k = 0; k < H; k++) {
        float w = __ldg(W + k*H + f);
        ull wd = pack2(w, w);
        const ulonglong2* row = reinterpret_cast<const ulonglong2*>(S + k*SP);
#pragma unroll
        for (int q = 0; q < MP/2; q++) {
            ulonglong2 a = row[q];          // LDS.128: pairs (4q,4q+1),(4q+2,4q+3)
            fma2(acc[2*q+0], a.x, wd);
            fma2(acc[2*q+1], a.y, wd);
        }
    }
}

// One dense stage into transposed output: sO[f][m] = tanh(b[f] + sX^T W (+ sY^T W2))
template<bool CAT>
__device__ __forceinline__ void stage(const float* __restrict__ sX,
                                      const float* __restrict__ sY,
                                      const float* __restrict__ W,
                                      const float* __restrict__ b,
                                      float* __restrict__ sO, int f)
{
    ull acc[MP];
    float bias = __ldg(b + f);
    ull bd = pack2(bias, bias);
#pragma unroll
    for (int mp = 0; mp < MP; mp++) acc[mp] = bd;

    accum_t(sX, W, f, acc);
    if (CAT) accum_t(sY, W + H*H, f, acc);

    float* orow = sO + f*SP;
#pragma unroll
    for (int mp = 0; mp < MP; mp++) {
        float2 p = unpack2(acc[mp]);
        float2 o = make_float2(htanh(p.x), htanh(p.y));
        *reinterpret_cast<float2*>(orow + 2*mp) = o;   // st.shared.v2
    }
}

// base = tanh(nf @ W_embed + b_embed), written into emb (= d_out), [node][f] layout.
__global__ void __launch_bounds__(NT)
embed_kernel(const float* __restrict__ nf, const float* __restrict__ W,
             const float* __restrict__ b, float* __restrict__ out, int n_nodes)
{
    __shared__ float S[FEAT * SP];   // transposed: S[k][m]
    int t    = threadIdx.x;
    int f    = t;
    int base = blockIdx.x * MT;

    // load node feats transposed: S[k][m] = nf[base+m][k]
    for (int i = t; i < MT * FEAT; i += NT) {
        int m = i / FEAT, k = i % FEAT;
        int row = base + m;
        if (row >= n_nodes) row = n_nodes - 1;
        S[k * SP + m] = nf[(long)row * FEAT + k];
    }
    __syncthreads();

    ull acc[MP];
    float bias = __ldg(b + f);
    ull bd = pack2(bias, bias);
#pragma unroll
    for (int mp = 0; mp < MP; mp++) acc[mp] = bd;

#pragma unroll 2
    for (int k = 0; k < FEAT; k++) {
        float w = __ldg(W + k*H + f);
        ull wd = pack2(w, w);
        const ulonglong2* row = reinterpret_cast<const ulonglong2*>(S + k*SP);
#pragma unroll
        for (int q = 0; q < MP/2; q++) {
            ulonglong2 a = row[q];
            fma2(acc[2*q+0], a.x, wd);
            fma2(acc[2*q+1], a.y, wd);
        }
    }
#pragma unroll
    for (int mp = 0; mp < MP; mp++) {
        float2 p = unpack2(acc[mp]);
        int r0 = base + 2*mp, r1 = base + 2*mp + 1;
        if (r0 < n_nodes) out[(long)r0 * H + f] = htanh(p.x);
        if (r1 < n_nodes) out[(long)r1 * H + f] = htanh(p.y);
    }
}

// Full GNN layer l: gather(K=8) -> 11 dense-tanh stages (transposed smem) -> write block l.
__global__ void __launch_bounds__(NT)
layer_kernel(float* emb,
             const int* __restrict__ src, int l,
             const float* __restrict__ Wmp0, const float* __restrict__ bmp0,
             const float* __restrict__ Wmp1, const float* __restrict__ bmp1,
             const float* __restrict__ Wmpc, const float* __restrict__ bmpc,
             const float* __restrict__ Wne0, const float* __restrict__ bne0,
             const float* __restrict__ Wne1, const float* __restrict__ bne1,
             const float* __restrict__ Wnec, const float* __restrict__ bnec)
{
    __shared__ float A[H * SP];
    __shared__ float B[H * SP];
    __shared__ float C[H * SP];
    __shared__ int   sidx[MT * KN];

    int t  = threadIdx.x;
    int f  = t;
    int d0 = blockIdx.x * MT;

    const int* __restrict__ srcL = src + (long)(l - 1) * NPL * KN;
    for (int i = t; i < MT * KN; i += NT) {
        int node = d0 + i / KN;
        if (node >= NPL) node = NPL - 1;
        sidx[i] = srcL[(long)node * KN + (i % KN)];
    }
    __syncthreads();

    // gather: A[f][m] = sum_k emb[src[m][k]][f]  (coalesced LDG across f)
#pragma unroll 1
    for (int m = 0; m < MT; m++) {
        float s = 0.f;
#pragma unroll
        for (int k = 0; k < KN; k++) {
            int row = sidx[m * KN + k];
            s += emb[(long)row * H + f];
        }
        A[f * SP + m] = s;
    }
    __syncthreads();

    // message-passing MLP
    stage<false>(A, nullptr, Wmp0, bmp0, B, f); __syncthreads();          // r0 -> B
    stage<false>(B, nullptr, Wmp1, bmp1, C, f); __syncthreads();          // r  -> C
    stage<true >(C, B, Wmpc + 0*2*H*H, bmpc + 0*H, A, f); __syncthreads();
    stage<true >(A, B, Wmpc + 1*2*H*H, bmpc + 1*H, C, f); __syncthreads();
    stage<true >(C, B, Wmpc + 2*2*H*H, bmpc + 2*H, A, f); __syncthreads();
    stage<true >(A, B, Wmpc + 3*2*H*H, bmpc + 3*H, C, f); __syncthreads(); // r -> C

    // this layer's base embedding -> A (transposed)
#pragma unroll 1
    for (int m = 0; m < MT; m++) {
        int node = d0 + m;
        if (node >= NPL) node = NPL - 1;
        A[f * SP + m] = emb[(long)(l * NPL + node) * H + f];
    }
    __syncthreads();

    // node-embedding MLP
    stage<true >(A, C, Wne0, bne0, B, f); __syncthreads();                // c0 -> B
    stage<false>(B, nullptr, Wne1, bne1, A, f); __syncthreads();          // e  -> A
    stage<true >(A, B, Wnec + 0*2*H*H, bnec + 0*H, C, f); __syncthreads();
    stage<true >(C, B, Wnec + 1*2*H*H, bnec + 1*H, A, f); __syncthreads();
    stage<true >(A, B, Wnec + 2*2*H*H, bnec + 2*H, C, f); __syncthreads();
    stage<true >(C, B, Wnec + 3*2*H*H, bnec + 3*H, A, f); __syncthreads(); // e -> A

    // write out: emb[l*NPL+node][f] = A[f][m]  (coalesced across f)
#pragma unroll 1
    for (int m = 0; m < MT; m++) {
        int node = d0 + m;
        if (node < NPL)
            emb[(long)(l * NPL + node) * H + f] = A[f * SP + m];
    }
}

extern "C" void kernel_launch(void* const* d_in, const int* in_sizes, int n_in,
                              void* d_out, int out_size)
{
    const float* nf      = (const float*)d_in[0];
    const int*   src     = (const int*)  d_in[1];
    const float* W_embed = (const float*)d_in[3];
    const float* b_embed = (const float*)d_in[4];
    const float* W_mp0   = (const float*)d_in[5];
    const float* b_mp0   = (const float*)d_in[6];
    const float* W_mp1   = (const float*)d_in[7];
    const float* b_mp1   = (const float*)d_in[8];
    const float* W_mpc   = (const float*)d_in[9];
    const float* b_mpc   = (const float*)d_in[10];
    const float* W_ne0   = (const float*)d_in[11];
    const float* b_ne0   = (const float*)d_in[12];
    const float* W_ne1   = (const float*)d_in[13];
    const float* b_ne1   = (const float*)d_in[14];
    const float* W_nec   = (const float*)d_in[15];
    const float* b_nec   = (const float*)d_in[16];

    float* out = (float*)d_out;

    const int n_nodes = L_TOT * NPL;
    embed_kernel<<<(n_nodes + MT - 1) / MT, NT>>>(nf, W_embed, b_embed, out, n_nodes);

    const int layer_blocks = (NPL + MT - 1) / MT;
    for (int l = 1; l < L_TOT; l++) {
        layer_kernel<<<layer_blocks, NT>>>(out, src, l,
                                           W_mp0, b_mp0, W_mp1, b_mp1, W_mpc, b_mpc,
                                           W_ne0, b_ne0, W_ne1, b_ne1, W_nec, b_nec);
    }
}

// round 4
// speedup vs baseline: 1.0222x; 1.0222x over previous
#include <cuda_runtime.h>

#define NPL   50000
#define L_TOT 6
#define KN    8
#define FEAT  32
#define H     128
#define MT    32      // nodes per block
#define NT    128     // threads = H; thread t owns output feature f = t
#define SROW  132     // smem row stride in floats (528B, 16B-aligned)
#define FROW  36      // embed smem row stride

typedef unsigned long long ull;

__device__ __forceinline__ ull pack2(float x, float y) {
    ull r; asm("mov.b64 %0, {%1, %2};" : "=l"(r) : "f"(x), "f"(y)); return r;
}
__device__ __forceinline__ void fma2(ull& acc, ull a, ull b) {
    asm("fma.rn.f32x2 %0, %1, %2, %0;" : "+l"(acc) : "l"(a), "l"(b));
}
__device__ __forceinline__ float2 unpack2(ull v) {
    float2 f; asm("mov.b64 {%0, %1}, %2;" : "=f"(f.x), "=f"(f.y) : "l"(v)); return f;
}
__device__ __forceinline__ float htanh(float x) {
    float y; asm("tanh.approx.f32 %0, %1;" : "=f"(y) : "f"(x)); return y;
}

// acc[m] += (even-k / odd-k packed partial sums of) S[m][:] . W[:][f]
// S node-major [m][k], row stride SROW. One broadcast LDS.128 -> 2 FFMA2 per m.
__device__ __forceinline__ void accum(const float* __restrict__ S,
                                      const float* __restrict__ W,
                                      int f, ull acc[MT])
{
#pragma unroll 2
    for (int k = 0; k < H; k += 4) {
        float w0 = W[(k+0)*H + f];
        float w1 = W[(k+1)*H + f];
        float w2 = W[(k+2)*H + f];
        float w3 = W[(k+3)*H + f];
        ull w01 = pack2(w0, w1);
        ull w23 = pack2(w2, w3);
#pragma unroll
        for (int m = 0; m < MT; m++) {
            ulonglong2 a = *reinterpret_cast<const ulonglong2*>(S + m*SROW + k);
            fma2(acc[m], a.x, w01);
            fma2(acc[m], a.y, w23);
        }
    }
}

// sO[m][f] = tanh(b[f] + sX[m].W (+ sY[m].W2))
template<bool CAT>
__device__ __forceinline__ void stage(const float* __restrict__ sX,
                                      const float* __restrict__ sY,
                                      const float* __restrict__ W,
                                      const float* __restrict__ b,
                                      float* __restrict__ sO, int f)
{
    ull acc[MT];
    float bias = b[f];
    ull binit = pack2(bias, 0.f);
#pragma unroll
    for (int m = 0; m < MT; m++) acc[m] = binit;

    accum(sX, W, f, acc);
    if (CAT) accum(sY, W + H*H, f, acc);

#pragma unroll
    for (int m = 0; m < MT; m++) {
        float2 p = unpack2(acc[m]);
        sO[m*SROW + f] = htanh(p.x + p.y);
    }
}

// base = tanh(nf @ W_embed + b_embed) -> emb (= d_out)
__global__ void __launch_bounds__(NT)
embed_kernel(const float* __restrict__ nf, const float* __restrict__ W,
             const float* __restrict__ b, float* __restrict__ out, int n_nodes)
{
    __shared__ float S[MT * FROW];
    int t    = threadIdx.x;
    int f    = t;
    int base = blockIdx.x * MT;

    for (int i = t; i < MT * FEAT; i += NT) {
        int m = i / FEAT, k = i % FEAT;
        int row = base + m;
        if (row >= n_nodes) row = n_nodes - 1;
        S[m * FROW + k] = nf[(long)row * FEAT + k];
    }
    __syncthreads();

    ull acc[MT];
    float bias = b[f];
    ull binit = pack2(bias, 0.f);
#pragma unroll
    for (int m = 0; m < MT; m++) acc[m] = binit;

#pragma unroll 2
    for (int k = 0; k < FEAT; k += 4) {
        float w0 = W[(k+0)*H + f];
        float w1 = W[(k+1)*H + f];
        float w2 = W[(k+2)*H + f];
        float w3 = W[(k+3)*H + f];
        ull w01 = pack2(w0, w1);
        ull w23 = pack2(w2, w3);
#pragma unroll
        for (int m = 0; m < MT; m++) {
            ulonglong2 a = *reinterpret_cast<const ulonglong2*>(S + m*FROW + k);
            fma2(acc[m], a.x, w01);
            fma2(acc[m], a.y, w23);
        }
    }
#pragma unroll
    for (int m = 0; m < MT; m++) {
        int row = base + m;
        if (row < n_nodes) {
            float2 p = unpack2(acc[m]);
            out[(long)row * H + f] = htanh(p.x + p.y);
        }
    }
}

// Full GNN layer l: gather(K=8) -> 11 dense-tanh stages -> write emb block l.
__global__ void __launch_bounds__(NT)
layer_kernel(float* emb,
             const int* __restrict__ src, int l,
             const float* __restrict__ Wmp0, const float* __restrict__ bmp0,
             const float* __restrict__ Wmp1, const float* __restrict__ bmp1,
             const float* __restrict__ Wmpc, const float* __restrict__ bmpc,
             const float* __restrict__ Wne0, const float* __restrict__ bne0,
             const float* __restrict__ Wne1, const float* __restrict__ bne1,
             const float* __restrict__ Wnec, const float* __restrict__ bnec)
{
    __shared__ float A[MT * SROW];
    __shared__ float B[MT * SROW];
    __shared__ float C[MT * SROW];
    __shared__ int   sidx[MT * KN];

    int t  = threadIdx.x;
    int f  = t;
    int d0 = blockIdx.x * MT;

    const int* __restrict__ srcL = src + (long)(l - 1) * NPL * KN;
    for (int i = t; i < MT * KN; i += NT) {
        int node = d0 + i / KN;
        if (node >= NPL) node = NPL - 1;
        sidx[i] = srcL[(long)node * KN + (i % KN)];
    }
    __syncthreads();

    // gather: A[m][f] = sum over 8 neighbors (coalesced LDG across f)
#pragma unroll 1
    for (int m = 0; m < MT; m++) {
        float s = 0.f;
#pragma unroll
        for (int k = 0; k < KN; k++) {
            int row = sidx[m * KN + k];
            s += emb[(long)row * H + f];
        }
        A[m * SROW + f] = s;
    }
    __syncthreads();

    // message-passing MLP
    stage<false>(A, nullptr, Wmp0, bmp0, B, f); __syncthreads();          // r0 -> B
    stage<false>(B, nullptr, Wmp1, bmp1, C, f); __syncthreads();          // r  -> C
    stage<true >(C, B, Wmpc + 0*2*H*H, bmpc + 0*H, A, f); __syncthreads();
    stage<true >(A, B, Wmpc + 1*2*H*H, bmpc + 1*H, C, f); __syncthreads();
    stage<true >(C, B, Wmpc + 2*2*H*H, bmpc + 2*H, A, f); __syncthreads();
    stage<true >(A, B, Wmpc + 3*2*H*H, bmpc + 3*H, C, f); __syncthreads(); // r -> C

    // this layer's base embedding -> A
#pragma unroll 1
    for (int m = 0; m < MT; m++) {
        int node = d0 + m;
        if (node >= NPL) node = NPL - 1;
        A[m * SROW + f] = emb[(long)(l * NPL + node) * H + f];
    }
    __syncthreads();

    // node-embedding MLP
    stage<true >(A, C, Wne0, bne0, B, f); __syncthreads();                // c0 -> B
    stage<false>(B, nullptr, Wne1, bne1, A, f); __syncthreads();          // e  -> A
    stage<true >(A, B, Wnec + 0*2*H*H, bnec + 0*H, C, f); __syncthreads();
    stage<true >(C, B, Wnec + 1*2*H*H, bnec + 1*H, A, f); __syncthreads();
    stage<true >(A, B, Wnec + 2*2*H*H, bnec + 2*H, C, f); __syncthreads();
    stage<true >(C, B, Wnec + 3*2*H*H, bnec + 3*H, A, f); __syncthreads(); // e -> A

#pragma unroll 1
    for (int m = 0; m < MT; m++) {
        int node = d0 + m;
        if (node < NPL)
            emb[(long)(l * NPL + node) * H + f] = A[m * SROW + f];
    }
}

extern "C" void kernel_launch(void* const* d_in, const int* in_sizes, int n_in,
                              void* d_out, int out_size)
{
    const float* nf      = (const float*)d_in[0];
    const int*   src     = (const int*)  d_in[1];
    const float* W_embed = (const float*)d_in[3];
    const float* b_embed = (const float*)d_in[4];
    const float* W_mp0   = (const float*)d_in[5];
    const float* b_mp0   = (const float*)d_in[6];
    const float* W_mp1   = (const float*)d_in[7];
    const float* b_mp1   = (const float*)d_in[8];
    const float* W_mpc   = (const float*)d_in[9];
    const float* b_mpc   = (const float*)d_in[10];
    const float* W_ne0   = (const float*)d_in[11];
    const float* b_ne0   = (const float*)d_in[12];
    const float* W_ne1   = (const float*)d_in[13];
    const float* b_ne1   = (const float*)d_in[14];
    const float* W_nec   = (const float*)d_in[15];
    const float* b_nec   = (const float*)d_in[16];

    float* out = (float*)d_out;

    const int n_nodes = L_TOT * NPL;
    embed_kernel<<<(n_nodes + MT - 1) / MT, NT>>>(nf, W_embed, b_embed, out, n_nodes);

    const int layer_blocks = (NPL + MT - 1) / MT;
    for (int l = 1; l < L_TOT; l++) {
        layer_kernel<<<layer_blocks, NT>>>(out, src, l,
                                           W_mp0, b_mp0, W_mp1, b_mp1, W_mpc, b_mpc,
                                           W_ne0, b_ne0, W_ne1, b_ne1, W_nec, b_nec);
    }
}

// round 5
// speedup vs baseline: 1.1726x; 1.1471x over previous
#include <cuda_runtime.h>

#define NPL   50000
#define L_TOT 6
#define KN    8
#define FEAT  32
#define H     128
#define MT    32      // nodes per block
#define NT    128     // 4 warps
#define SROW  132     // smem row stride (floats): 528B, 16B-aligned
#define FROW  36
#define TM    8       // nodes per warp (all lanes share them)
#define TF    4       // features per lane

// packed-weight segment offsets, in k-pair rows (each H-chunk = 64 rows)
#define KP_MP0   0
#define KP_MP1   64
#define KP_MPC   128    // + i*128
#define KP_NE0   640
#define KP_NE1   768
#define KP_NEC   832    // + i*128
#define KP_TOTAL 1344

typedef unsigned long long ull;

__device__ ull g_Wp[KP_TOTAL * H];   // [kp][f] = pack(W[2kp][f], W[2kp+1][f])

__device__ __forceinline__ ull pack2(float x, float y) {
    ull r; asm("mov.b64 %0, {%1, %2};" : "=l"(r) : "f"(x), "f"(y)); return r;
}
__device__ __forceinline__ void fma2(ull& acc, ull a, ull b) {
    asm("fma.rn.f32x2 %0, %1, %2, %0;" : "+l"(acc) : "l"(a), "l"(b));
}
__device__ __forceinline__ float2 unpack2(ull v) {
    float2 f; asm("mov.b64 {%0, %1}, %2;" : "=f"(f.x), "=f"(f.y) : "l"(v)); return f;
}
__device__ __forceinline__ float htanh(float x) {
    float y; asm("tanh.approx.f32 %0, %1;" : "=f"(y) : "f"(x)); return y;
}

// one-time weight packing (runs inside the graph every launch; deterministic)
__global__ void pack_weights(const float* __restrict__ Wmp0, const float* __restrict__ Wmp1,
                             const float* __restrict__ Wmpc, const float* __restrict__ Wne0,
                             const float* __restrict__ Wne1, const float* __restrict__ Wnec)
{
    int idx = blockIdx.x * blockDim.x + threadIdx.x;
    if (idx >= KP_TOTAL * H) return;
    int kp = idx / H, f = idx % H;
    const float* src; int local;
    if      (kp < KP_MP1) { src = Wmp0;                                local = kp; }
    else if (kp < KP_MPC) { src = Wmp1;                                local = kp - KP_MP1; }
    else if (kp < KP_NE0) { src = Wmpc + ((kp - KP_MPC) / 128) * 2*H*H; local = (kp - KP_MPC) % 128; }
    else if (kp < KP_NE1) { src = Wne0;                                local = kp - KP_NE0; }
    else if (kp < KP_NEC) { src = Wne1;                                local = kp - KP_NE1; }
    else                  { src = Wnec + ((kp - KP_NEC) / 128) * 2*H*H; local = (kp - KP_NEC) % 128; }
    int k = 2 * local;
    g_Wp[idx] = pack2(src[k * H + f], src[(k + 1) * H + f]);
}

// acc[m][j] += packed(even-k, odd-k) partials of S[m0+m][:] . W[:][f4+j]
__device__ __forceinline__ void accum(const float* __restrict__ S,
                                      const ull* __restrict__ Wp,
                                      int f4, int m0, ull acc[TM][TF])
{
#pragma unroll 1
    for (int kp = 0; kp < H/2; kp += 2) {
        ulonglong2 wA0 = *reinterpret_cast<const ulonglong2*>(Wp + (size_t)kp*H + f4);
        ulonglong2 wA1 = *reinterpret_cast<const ulonglong2*>(Wp + (size_t)kp*H + f4 + 2);
        ulonglong2 wB0 = *reinterpret_cast<const ulonglong2*>(Wp + (size_t)(kp+1)*H + f4);
        ulonglong2 wB1 = *reinterpret_cast<const ulonglong2*>(Wp + (size_t)(kp+1)*H + f4 + 2);
#pragma unroll
        for (int m = 0; m < TM; m++) {
            ulonglong2 a = *reinterpret_cast<const ulonglong2*>(S + (m0 + m)*SROW + kp*2);
            fma2(acc[m][0], a.x, wA0.x);
            fma2(acc[m][1], a.x, wA0.y);
            fma2(acc[m][2], a.x, wA1.x);
            fma2(acc[m][3], a.x, wA1.y);
            fma2(acc[m][0], a.y, wB0.x);
            fma2(acc[m][1], a.y, wB0.y);
            fma2(acc[m][2], a.y, wB1.x);
            fma2(acc[m][3], a.y, wB1.y);
        }
    }
}

// sO[m][f] = tanh(b[f] + sX[m].W (+ sY[m].W2)); W given by kp-row offset into g_Wp
template<bool CAT>
__device__ __forceinline__ void stage(const float* __restrict__ sX,
                                      const float* __restrict__ sY,
                                      int kpOff, const float* __restrict__ b,
                                      float* __restrict__ sO, int f4, int m0)
{
    ull acc[TM][TF];
    float4 bb = *reinterpret_cast<const float4*>(b + f4);
#pragma unroll
    for (int m = 0; m < TM; m++) {
        acc[m][0] = pack2(bb.x, 0.f);
        acc[m][1] = pack2(bb.y, 0.f);
        acc[m][2] = pack2(bb.z, 0.f);
        acc[m][3] = pack2(bb.w, 0.f);
    }
    accum(sX, g_Wp + (size_t)kpOff * H, f4, m0, acc);
    if (CAT) accum(sY, g_Wp + (size_t)(kpOff + 64) * H, f4, m0, acc);

#pragma unroll
    for (int m = 0; m < TM; m++) {
        float2 p0 = unpack2(acc[m][0]);
        float2 p1 = unpack2(acc[m][1]);
        float2 p2 = unpack2(acc[m][2]);
        float2 p3 = unpack2(acc[m][3]);
        float4 o;
        o.x = htanh(p0.x + p0.y);
        o.y = htanh(p1.x + p1.y);
        o.z = htanh(p2.x + p2.y);
        o.w = htanh(p3.x + p3.y);
        *reinterpret_cast<float4*>(sO + (m0 + m)*SROW + f4) = o;
    }
}

// base = tanh(nf @ W_embed + b_embed) -> emb (= d_out)
__global__ void __launch_bounds__(NT)
embed_kernel(const float* __restrict__ nf, const float* __restrict__ W,
             const float* __restrict__ b, float* __restrict__ out, int n_nodes)
{
    __shared__ float S[MT * FROW];
    int t    = threadIdx.x;
    int f    = t;
    int base = blockIdx.x * MT;

    for (int i = t; i < MT * FEAT; i += NT) {
        int m = i / FEAT, k = i % FEAT;
        int row = base + m;
        if (row >= n_nodes) row = n_nodes - 1;
        S[m * FROW + k] = nf[(long)row * FEAT + k];
    }
    __syncthreads();

    ull acc[MT];
    float bias = b[f];
    ull binit = pack2(bias, 0.f);
#pragma unroll
    for (int m = 0; m < MT; m++) acc[m] = binit;

#pragma unroll 2
    for (int k = 0; k < FEAT; k += 4) {
        float w0 = W[(k+0)*H + f];
        float w1 = W[(k+1)*H + f];
        float w2 = W[(k+2)*H + f];
        float w3 = W[(k+3)*H + f];
        ull w01 = pack2(w0, w1);
        ull w23 = pack2(w2, w3);
#pragma unroll
        for (int m = 0; m < MT; m++) {
            ulonglong2 a = *reinterpret_cast<const ulonglong2*>(S + m*FROW + k);
            fma2(acc[m], a.x, w01);
            fma2(acc[m], a.y, w23);
        }
    }
#pragma unroll
    for (int m = 0; m < MT; m++) {
        int row = base + m;
        if (row < n_nodes) {
            float2 p = unpack2(acc[m]);
            out[(long)row * H + f] = htanh(p.x + p.y);
        }
    }
}

// Full GNN layer l
__global__ void __launch_bounds__(NT, 4)
layer_kernel(float* emb, const int* __restrict__ src, int l,
             const float* __restrict__ bmp0, const float* __restrict__ bmp1,
             const float* __restrict__ bmpc,
             const float* __restrict__ bne0, const float* __restrict__ bne1,
             const float* __restrict__ bnec)
{
    __shared__ float A[MT * SROW];
    __shared__ float B[MT * SROW];
    __shared__ float C[MT * SROW];
    __shared__ int   sidx[MT * KN];

    int t    = threadIdx.x;
    int lane = t & 31;
    int wrp  = t >> 5;
    int f4   = lane * 4;
    int m0   = wrp * TM;
    int d0   = blockIdx.x * MT;

    const int* __restrict__ srcL = src + (long)(l - 1) * NPL * KN;
    for (int i = t; i < MT * KN; i += NT) {
        int node = d0 + i / KN;
        if (node >= NPL) node = NPL - 1;
        sidx[i] = srcL[(long)node * KN + (i % KN)];
    }
    __syncthreads();

    // gather: A[m][t] = sum over 8 neighbors (coalesced across t)
#pragma unroll 1
    for (int m = 0; m < MT; m++) {
        float s = 0.f;
#pragma unroll
        for (int k = 0; k < KN; k++) {
            int row = sidx[m * KN + k];
            s += emb[(long)row * H + t];
        }
        A[m * SROW + t] = s;
    }
    __syncthreads();

    // message-passing MLP
    stage<false>(A, nullptr, KP_MP0, bmp0, B, f4, m0); __syncthreads();      // r0 -> B
    stage<false>(B, nullptr, KP_MP1, bmp1, C, f4, m0); __syncthreads();      // r  -> C
    stage<true >(C, B, KP_MPC + 0*128, bmpc + 0*H, A, f4, m0); __syncthreads();
    stage<true >(A, B, KP_MPC + 1*128, bmpc + 1*H, C, f4, m0); __syncthreads();
    stage<true >(C, B, KP_MPC + 2*128, bmpc + 2*H, A, f4, m0); __syncthreads();
    stage<true >(A, B, KP_MPC + 3*128, bmpc + 3*H, C, f4, m0); __syncthreads(); // r -> C

    // this layer's base embedding -> A
#pragma unroll 1
    for (int m = 0; m < MT; m++) {
        int node = d0 + m;
        if (node >= NPL) node = NPL - 1;
        A[m * SROW + t] = emb[(long)(l * NPL + node) * H + t];
    }
    __syncthreads();

    // node-embedding MLP
    stage<true >(A, C, KP_NE0, bne0, B, f4, m0); __syncthreads();            // c0 -> B
    stage<false>(B, nullptr, KP_NE1, bne1, A, f4, m0); __syncthreads();      // e  -> A
    stage<true >(A, B, KP_NEC + 0*128, bnec + 0*H, C, f4, m0); __syncthreads();
    stage<true >(C, B, KP_NEC + 1*128, bnec + 1*H, A, f4, m0); __syncthreads();
    stage<true >(A, B, KP_NEC + 2*128, bnec + 2*H, C, f4, m0); __syncthreads();
    stage<true >(C, B, KP_NEC + 3*128, bnec + 3*H, A, f4, m0); __syncthreads(); // e -> A

#pragma unroll 1
    for (int m = 0; m < MT; m++) {
        int node = d0 + m;
        if (node < NPL)
            emb[(long)(l * NPL + node) * H + t] = A[m * SROW + t];
    }
}

extern "C" void kernel_launch(void* const* d_in, const int* in_sizes, int n_in,
                              void* d_out, int out_size)
{
    const float* nf      = (const float*)d_in[0];
    const int*   src     = (const int*)  d_in[1];
    const float* W_embed = (const float*)d_in[3];
    const float* b_embed = (const float*)d_in[4];
    const float* W_mp0   = (const float*)d_in[5];
    const float* b_mp0   = (const float*)d_in[6];
    const float* W_mp1   = (const float*)d_in[7];
    const float* b_mp1   = (const float*)d_in[8];
    const float* W_mpc   = (const float*)d_in[9];
    const float* b_mpc   = (const float*)d_in[10];
    const float* W_ne0   = (const float*)d_in[11];
    const float* b_ne0   = (const float*)d_in[12];
    const float* W_ne1   = (const float*)d_in[13];
    const float* b_ne1   = (const float*)d_in[14];
    const float* W_nec   = (const float*)d_in[15];
    const float* b_nec   = (const float*)d_in[16];

    float* out = (float*)d_out;

    pack_weights<<<(KP_TOTAL * H + 255) / 256, 256>>>(W_mp0, W_mp1, W_mpc, W_ne0, W_ne1, W_nec);

    const int n_nodes = L_TOT * NPL;
    embed_kernel<<<(n_nodes + MT - 1) / MT, NT>>>(nf, W_embed, b_embed, out, n_nodes);

    const int layer_blocks = (NPL + MT - 1) / MT;
    for (int l = 1; l < L_TOT; l++) {
        layer_kernel<<<layer_blocks, NT>>>(out, src, l,
                                           b_mp0, b_mp1, b_mpc, b_ne0, b_ne1, b_nec);
    }
}

// round 6
// speedup vs baseline: 1.2588x; 1.0735x over previous
#include <cuda_runtime.h>

#define NPL   50000
#define L_TOT 6
#define KN    8
#define FEAT  32
#define H     128
#define MT    32      // nodes per block
#define NT    128     // 4 warps; lane owns features f4..f4+3, warp owns 8 nodes
#define FROW  36
#define TM    8       // nodes per warp
#define TF    4       // features per lane

// packed-weight segment offsets, in k-pair rows (each H-chunk = 64 rows)
#define KP_MP0   0
#define KP_MP1   64
#define KP_MPC   128    // + i*128
#define KP_NE0   640
#define KP_NE1   768
#define KP_NEC   832    // + i*128
#define KP_TOTAL 1344

typedef unsigned long long ull;

__device__ ull g_Wp[KP_TOTAL * H];   // [kp][f] = pack(W[2kp][f], W[2kp+1][f])

__device__ __forceinline__ ull pack2(float x, float y) {
    ull r; asm("mov.b64 %0, {%1, %2};" : "=l"(r) : "f"(x), "f"(y)); return r;
}
__device__ __forceinline__ void fma2(ull& acc, ull a, ull b) {
    asm("fma.rn.f32x2 %0, %1, %2, %0;" : "+l"(acc) : "l"(a), "l"(b));
}
__device__ __forceinline__ float2 unpack2(ull v) {
    float2 f; asm("mov.b64 {%0, %1}, %2;" : "=f"(f.x), "=f"(f.y) : "l"(v)); return f;
}
__device__ __forceinline__ float htanh(float x) {
    float y; asm("tanh.approx.f32 %0, %1;" : "=f"(y) : "f"(x)); return y;
}

// one-time weight packing (inside the graph each launch; deterministic)
__global__ void pack_weights(const float* __restrict__ Wmp0, const float* __restrict__ Wmp1,
                             const float* __restrict__ Wmpc, const float* __restrict__ Wne0,
                             const float* __restrict__ Wne1, const float* __restrict__ Wnec)
{
    int idx = blockIdx.x * blockDim.x + threadIdx.x;
    if (idx >= KP_TOTAL * H) return;
    int kp = idx / H, f = idx % H;
    const float* src; int local;
    if      (kp < KP_MP1) { src = Wmp0;                                 local = kp; }
    else if (kp < KP_MPC) { src = Wmp1;                                 local = kp - KP_MP1; }
    else if (kp < KP_NE0) { src = Wmpc + ((kp - KP_MPC) / 128) * 2*H*H; local = (kp - KP_MPC) % 128; }
    else if (kp < KP_NE1) { src = Wne0;                                 local = kp - KP_NE0; }
    else if (kp < KP_NEC) { src = Wne1;                                 local = kp - KP_NE1; }
    else                  { src = Wnec + ((kp - KP_NEC) / 128) * 2*H*H; local = (kp - KP_NEC) % 128; }
    int k = 2 * local;
    g_Wp[idx] = pack2(src[k * H + f], src[(k + 1) * H + f]);
}

// acc[m][j] += packed(even-k, odd-k) partials of S[m0+m][:] . W[:][f4+j]
// S row stride = H (broadcast LDS, conflict-free). Zero MOVs in the loop.
__device__ __forceinline__ void accum(const float* __restrict__ S,
                                      const ull* __restrict__ Wp,
                                      int f4, int m0, ull acc[TM][TF])
{
#pragma unroll 2
    for (int kp = 0; kp < H/2; kp += 2) {
        ulonglong2 wA0 = __ldg(reinterpret_cast<const ulonglong2*>(Wp + (size_t)kp*H + f4));
        ulonglong2 wA1 = __ldg(reinterpret_cast<const ulonglong2*>(Wp + (size_t)kp*H + f4 + 2));
        ulonglong2 wB0 = __ldg(reinterpret_cast<const ulonglong2*>(Wp + (size_t)(kp+1)*H + f4));
        ulonglong2 wB1 = __ldg(reinterpret_cast<const ulonglong2*>(Wp + (size_t)(kp+1)*H + f4 + 2));
#pragma unroll
        for (int m = 0; m < TM; m++) {
            ulonglong2 a = *reinterpret_cast<const ulonglong2*>(S + (m0 + m)*H + kp*2);
            fma2(acc[m][0], a.x, wA0.x);
            fma2(acc[m][1], a.x, wA0.y);
            fma2(acc[m][2], a.x, wA1.x);
            fma2(acc[m][3], a.x, wA1.y);
            fma2(acc[m][0], a.y, wB0.x);
            fma2(acc[m][1], a.y, wB0.y);
            fma2(acc[m][2], a.y, wB1.x);
            fma2(acc[m][3], a.y, wB1.y);
        }
    }
}

// warp-local dense stage: sO rows m0..m0+7 = tanh(b + sX.W (+ sY.W2))
template<bool CAT>
__device__ __forceinline__ void stage(const float* __restrict__ sX,
                                      const float* __restrict__ sY,
                                      int kpOff, const float* __restrict__ b,
                                      float* __restrict__ sO, int f4, int m0)
{
    ull acc[TM][TF];
    float4 bb = __ldg(reinterpret_cast<const float4*>(b + f4));
#pragma unroll
    for (int m = 0; m < TM; m++) {
        acc[m][0] = pack2(bb.x, 0.f);
        acc[m][1] = pack2(bb.y, 0.f);
        acc[m][2] = pack2(bb.z, 0.f);
        acc[m][3] = pack2(bb.w, 0.f);
    }
    accum(sX, g_Wp + (size_t)kpOff * H, f4, m0, acc);
    if (CAT) accum(sY, g_Wp + (size_t)(kpOff + 64) * H, f4, m0, acc);

#pragma unroll
    for (int m = 0; m < TM; m++) {
        float2 p0 = unpack2(acc[m][0]);
        float2 p1 = unpack2(acc[m][1]);
        float2 p2 = unpack2(acc[m][2]);
        float2 p3 = unpack2(acc[m][3]);
        float4 o;
        o.x = htanh(p0.x + p0.y);
        o.y = htanh(p1.x + p1.y);
        o.z = htanh(p2.x + p2.y);
        o.w = htanh(p3.x + p3.y);
        *reinterpret_cast<float4*>(sO + (m0 + m)*H + f4) = o;
    }
    __syncwarp();
}

// base = tanh(nf @ W_embed + b_embed) -> emb (= d_out)
__global__ void __launch_bounds__(NT)
embed_kernel(const float* __restrict__ nf, const float* __restrict__ W,
             const float* __restrict__ b, float* __restrict__ out, int n_nodes)
{
    __shared__ float S[MT * FROW];
    int t    = threadIdx.x;
    int f    = t;
    int base = blockIdx.x * MT;

    for (int i = t; i < MT * FEAT; i += NT) {
        int m = i / FEAT, k = i % FEAT;
        int row = base + m;
        if (row >= n_nodes) row = n_nodes - 1;
        S[m * FROW + k] = nf[(long)row * FEAT + k];
    }
    __syncthreads();

    ull acc[MT];
    float bias = b[f];
    ull binit = pack2(bias, 0.f);
#pragma unroll
    for (int m = 0; m < MT; m++) acc[m] = binit;

#pragma unroll 2
    for (int k = 0; k < FEAT; k += 4) {
        float w0 = W[(k+0)*H + f];
        float w1 = W[(k+1)*H + f];
        float w2 = W[(k+2)*H + f];
        float w3 = W[(k+3)*H + f];
        ull w01 = pack2(w0, w1);
        ull w23 = pack2(w2, w3);
#pragma unroll
        for (int m = 0; m < MT; m++) {
            ulonglong2 a = *reinterpret_cast<const ulonglong2*>(S + m*FROW + k);
            fma2(acc[m], a.x, w01);
            fma2(acc[m], a.y, w23);
        }
    }
#pragma unroll
    for (int m = 0; m < MT; m++) {
        int row = base + m;
        if (row < n_nodes) {
            float2 p = unpack2(acc[m]);
            out[(long)row * H + f] = htanh(p.x + p.y);
        }
    }
}

// Full GNN layer l — fully warp-independent, zero __syncthreads.
__global__ void __launch_bounds__(NT, 4)
layer_kernel(float* emb, const int* __restrict__ src, int l,
             const float* __restrict__ bmp0, const float* __restrict__ bmp1,
             const float* __restrict__ bmpc,
             const float* __restrict__ bne0, const float* __restrict__ bne1,
             const float* __restrict__ bnec)
{
    __shared__ float A[MT * H];
    __shared__ float B[MT * H];
    __shared__ float C[MT * H];
    __shared__ int   sidx[MT * KN];

    int t    = threadIdx.x;
    int lane = t & 31;
    int wrp  = t >> 5;
    int f4   = lane * 4;
    int m0   = wrp * TM;
    int d0   = blockIdx.x * MT;

    // warp-local edge index load: 64 ints per warp
    const int* __restrict__ srcL = src + (long)(l - 1) * NPL * KN;
    {
        int* sw = sidx + wrp * (TM * KN);
#pragma unroll
        for (int j = 0; j < 2; j++) {
            int i = lane + j * 32;             // 0..63
            int node = d0 + m0 + i / KN;
            if (node >= NPL) node = NPL - 1;
            sw[i] = srcL[(long)node * KN + (i % KN)];
        }
    }
    __syncwarp();

    // warp-local gather: A[m0+m][f4..] = sum of 8 neighbor rows (float4 LDG, L2-hot)
    {
        const int* sw = sidx + wrp * (TM * KN);
#pragma unroll 2
        for (int m = 0; m < TM; m++) {
            float4 s = make_float4(0.f, 0.f, 0.f, 0.f);
#pragma unroll
            for (int k = 0; k < KN; k++) {
                int row = sw[m * KN + k];
                float4 v = __ldg(reinterpret_cast<const float4*>(emb + (long)row * H + f4));
                s.x += v.x; s.y += v.y; s.z += v.z; s.w += v.w;
            }
            *reinterpret_cast<float4*>(A + (m0 + m)*H + f4) = s;
        }
    }
    __syncwarp();

    // message-passing MLP (all warp-local)
    stage<false>(A, nullptr, KP_MP0, bmp0, B, f4, m0);
    stage<false>(B, nullptr, KP_MP1, bmp1, C, f4, m0);
    stage<true >(C, B, KP_MPC + 0*128, bmpc + 0*H, A, f4, m0);
    stage<true >(A, B, KP_MPC + 1*128, bmpc + 1*H, C, f4, m0);
    stage<true >(C, B, KP_MPC + 2*128, bmpc + 2*H, A, f4, m0);
    stage<true >(A, B, KP_MPC + 3*128, bmpc + 3*H, C, f4, m0);   // r -> C

    // this layer's base embedding -> A (warp-local rows)
#pragma unroll
    for (int m = 0; m < TM; m++) {
        int node = d0 + m0 + m;
        if (node >= NPL) node = NPL - 1;
        *reinterpret_cast<float4*>(A + (m0 + m)*H + f4) =
            __ldg(reinterpret_cast<const float4*>(emb + (long)(l * NPL + node) * H + f4));
    }
    __syncwarp();

    // node-embedding MLP
    stage<true >(A, C, KP_NE0, bne0, B, f4, m0);                 // c0 -> B
    stage<false>(B, nullptr, KP_NE1, bne1, A, f4, m0);           // e  -> A
    stage<true >(A, B, KP_NEC + 0*128, bnec + 0*H, C, f4, m0);
    stage<true >(C, B, KP_NEC + 1*128, bnec + 1*H, A, f4, m0);
    stage<true >(A, B, KP_NEC + 2*128, bnec + 2*H, C, f4, m0);
    stage<true >(C, B, KP_NEC + 3*128, bnec + 3*H, A, f4, m0);   // e -> A

#pragma unroll
    for (int m = 0; m < TM; m++) {
        int node = d0 + m0 + m;
        if (node < NPL)
            *reinterpret_cast<float4*>(emb + (long)(l * NPL + node) * H + f4) =
                *reinterpret_cast<const float4*>(A + (m0 + m)*H + f4);
    }
}

extern "C" void kernel_launch(void* const* d_in, const int* in_sizes, int n_in,
                              void* d_out, int out_size)
{
    const float* nf      = (const float*)d_in[0];
    const int*   src     = (const int*)  d_in[1];
    const float* W_embed = (const float*)d_in[3];
    const float* b_embed = (const float*)d_in[4];
    const float* W_mp0   = (const float*)d_in[5];
    const float* b_mp0   = (const float*)d_in[6];
    const float* W_mp1   = (const float*)d_in[7];
    const float* b_mp1   = (const float*)d_in[8];
    const float* W_mpc   = (const float*)d_in[9];
    const float* b_mpc   = (const float*)d_in[10];
    const float* W_ne0   = (const float*)d_in[11];
    const float* b_ne0   = (const float*)d_in[12];
    const float* W_ne1   = (const float*)d_in[13];
    const float* b_ne1   = (const float*)d_in[14];
    const float* W_nec   = (const float*)d_in[15];
    const float* b_nec   = (const float*)d_in[16];

    float* out = (float*)d_out;

    pack_weights<<<(KP_TOTAL * H + 255) / 256, 256>>>(W_mp0, W_mp1, W_mpc, W_ne0, W_ne1, W_nec);

    const int n_nodes = L_TOT * NPL;
    embed_kernel<<<(n_nodes + MT - 1) / MT, NT>>>(nf, W_embed, b_embed, out, n_nodes);

    const int layer_blocks = (NPL + MT - 1) / MT;
    for (int l = 1; l < L_TOT; l++) {
        layer_kernel<<<layer_blocks, NT>>>(out, src, l,
                                           b_mp0, b_mp1, b_mpc, b_ne0, b_ne1, b_nec);
    }
}